// round 13
// baseline (speedup 1.0000x reference)
#include <cuda_runtime.h>
#include <cuda_bf16.h>
#include <cstdint>

#define D        256
#define NMAX     8192
#define BM       128
#define BN       128
#define QBLKS    (NMAX / BM)             // 64
#define KTILES   (NMAX / BN)             // 64
#define TOT_TILES (QBLKS * KTILES)       // 4096
#define GRID_SZ  148                     // one CTA per SM, balanced static ranges
#define THREADS  256                     // 8 warps, warp grid 4(M) x 2(N)
#define SPAD     264                     // 256 + 8 halves pad: conflict-free LDSM

#define LOG2E    1.4426950408889634f
#define LN2      0.6931471805599453f

// smem: [0..31] mbarriers (full0, full1, empty0, empty1), data from 128
#define MB_FULL0   0
#define MB_FULL1   8
#define MB_EMPTY0  16
#define MB_EMPTY1  24
#define DATA_OFF   128

__device__ __align__(16) __nv_bfloat16 g_Qn[(size_t)NMAX * D];
__device__ __align__(16) __nv_bfloat16 g_Kn[(size_t)NMAX * D];
__device__ float g_psum[NMAX];
__device__ float g_pdiag[NMAX];

// ---------------- helpers ----------------
__device__ __forceinline__ void cp_async16(void* smem_dst, const void* gmem_src) {
    uint32_t s = (uint32_t)__cvta_generic_to_shared(smem_dst);
    asm volatile("cp.async.cg.shared.global [%0], [%1], 16;\n" :: "r"(s), "l"(gmem_src));
}
// .noinc: one REAL arrival per thread (init count == #threads).
__device__ __forceinline__ void cp_mbar_arrive_noinc(uint32_t mbar) {
    asm volatile("cp.async.mbarrier.arrive.noinc.shared::cta.b64 [%0];"
                 :: "r"(mbar) : "memory");
}
__device__ __forceinline__ void cp_wait_all() {
    asm volatile("cp.async.wait_group 0;\n" ::: "memory");
}
__device__ __forceinline__ void mbar_init(uint32_t a, uint32_t cnt) {
    asm volatile("mbarrier.init.shared.b64 [%0], %1;" :: "r"(a), "r"(cnt) : "memory");
}
__device__ __forceinline__ void mbar_arrive(uint32_t a) {
    asm volatile("mbarrier.arrive.shared.b64 _, [%0];" :: "r"(a) : "memory");
}
__device__ __forceinline__ void mbar_wait(uint32_t a, uint32_t parity) {
    asm volatile("{\n\t.reg .pred P1;\n\t"
                 "WAIT_LOOP_%=:\n\t"
                 "mbarrier.try_wait.parity.acquire.cta.shared::cta.b64 P1, [%0], %1, 0x989680;\n\t"
                 "@P1 bra.uni WAIT_DONE_%=;\n\t"
                 "bra.uni WAIT_LOOP_%=;\n\t"
                 "WAIT_DONE_%=:\n\t}" :: "r"(a), "r"(parity) : "memory");
}
__device__ __forceinline__ void ldsm_x4(uint32_t& r0, uint32_t& r1,
                                        uint32_t& r2, uint32_t& r3, uint32_t addr) {
    asm volatile("ldmatrix.sync.aligned.m8n8.x4.shared.b16 {%0,%1,%2,%3}, [%4];"
                 : "=r"(r0), "=r"(r1), "=r"(r2), "=r"(r3) : "r"(addr));
}

// Load one [128 x 256 bf16] tile into SPAD-padded smem via cp.async (256 thr).
__device__ __forceinline__ void load_tile_async(__nv_bfloat16* s,
                                                const __nv_bfloat16* g, int tid) {
    const uint4* src = (const uint4*)g;
    #pragma unroll
    for (int i = tid; i < BM * 32; i += THREADS) {   // 32 x 16B chunks per row
        int r = i >> 5, c = i & 31;
        cp_async16(s + r * SPAD + c * 8, src + r * 32 + c);
    }
}

// ---------------------------------------------------------------------------
// Kernel 1: L2 normalize (one warp per TWO rows) + zero the partial arrays.
// Queries get 2*log2(e) folded in -> log2-domain logits, no max needed.
// ---------------------------------------------------------------------------
__global__ void normalize_kernel(const float* __restrict__ q,
                                 const float* __restrict__ k, int N) {
    // zero partial accumulators (ordering: same stream, before infonce)
    int gid = blockIdx.x * 256 + threadIdx.x;
    if (gid < NMAX) { g_psum[gid] = 0.f; g_pdiag[gid] = 0.f; }

    const int warp = threadIdx.x >> 5, lane = threadIdx.x & 31;
    const int row0 = blockIdx.x * 16 + warp * 2;     // grid = 2N/16
    const bool is_q = row0 < N;
    const int  r0   = is_q ? row0 : row0 - N;
    const float* srcb = is_q ? q : k;
    __nv_bfloat16* dstb = is_q ? g_Qn : g_Kn;

    const float4* sA = (const float4*)(srcb + (size_t)r0 * D);
    const float4* sB = (const float4*)(srcb + (size_t)(r0 + 1) * D);
    float4 a0 = sA[lane * 2], a1 = sA[lane * 2 + 1];
    float4 b0 = sB[lane * 2], b1 = sB[lane * 2 + 1];

    float ssA = a0.x*a0.x + a0.y*a0.y + a0.z*a0.z + a0.w*a0.w
              + a1.x*a1.x + a1.y*a1.y + a1.z*a1.z + a1.w*a1.w;
    float ssB = b0.x*b0.x + b0.y*b0.y + b0.z*b0.z + b0.w*b0.w
              + b1.x*b1.x + b1.y*b1.y + b1.z*b1.z + b1.w*b1.w;
    #pragma unroll
    for (int o = 16; o > 0; o >>= 1) {
        ssA += __shfl_xor_sync(0xffffffffu, ssA, o);
        ssB += __shfl_xor_sync(0xffffffffu, ssB, o);
    }

    float scA = rsqrtf(fmaxf(ssA, 1e-24f));
    float scB = rsqrtf(fmaxf(ssB, 1e-24f));
    if (is_q) { scA *= 2.0f * LOG2E; scB *= 2.0f * LOG2E; }

    uint4 oA, oB;
    {
        __nv_bfloat162 t0 = __float22bfloat162_rn({a0.x*scA, a0.y*scA});
        __nv_bfloat162 t1 = __float22bfloat162_rn({a0.z*scA, a0.w*scA});
        __nv_bfloat162 t2 = __float22bfloat162_rn({a1.x*scA, a1.y*scA});
        __nv_bfloat162 t3 = __float22bfloat162_rn({a1.z*scA, a1.w*scA});
        oA.x = *(uint32_t*)&t0; oA.y = *(uint32_t*)&t1;
        oA.z = *(uint32_t*)&t2; oA.w = *(uint32_t*)&t3;
    }
    {
        __nv_bfloat162 t0 = __float22bfloat162_rn({b0.x*scB, b0.y*scB});
        __nv_bfloat162 t1 = __float22bfloat162_rn({b0.z*scB, b0.w*scB});
        __nv_bfloat162 t2 = __float22bfloat162_rn({b1.x*scB, b1.y*scB});
        __nv_bfloat162 t3 = __float22bfloat162_rn({b1.z*scB, b1.w*scB});
        oB.x = *(uint32_t*)&t0; oB.y = *(uint32_t*)&t1;
        oB.z = *(uint32_t*)&t2; oB.w = *(uint32_t*)&t3;
    }
    ((uint4*)(dstb + (size_t)r0 * D))[lane]       = oA;
    ((uint4*)(dstb + (size_t)(r0 + 1) * D))[lane] = oB;
}

// ---------------------------------------------------------------------------
// Kernel 2: bf16 mma.sync GEMM + fused sum(2^logit). 148 CTAs; CTA i owns
// unit tiles [i*4096/148, (i+1)*4096/148) qb-major (27-28 tiles, balanced;
// <=1 A-reload per CTA). Epilogue uses ex2.approx.f16x2: two exponentials
// per MUFU op (halves the serialized MUFU phase); f16 tree depth <= 3 and
// terms <= 8*7.4 so no overflow; diag stays exact f32.
// ---------------------------------------------------------------------------
__global__ __launch_bounds__(THREADS, 1)
void infonce_kernel() {
    extern __shared__ __align__(16) char smem_raw[];
    const uint32_t sb = (uint32_t)__cvta_generic_to_shared(smem_raw);
    __nv_bfloat16* As  = (__nv_bfloat16*)(smem_raw + DATA_OFF); // 128 * SPAD
    __nv_bfloat16* Bs0 = As + BM * SPAD;                        // buf 0
    __nv_bfloat16* Bs1 = Bs0 + BN * SPAD;                       // buf 1
    __nv_bfloat16* Bbuf[2] = { Bs0, Bs1 };

    const uint32_t full_mb[2]  = { sb + MB_FULL0,  sb + MB_FULL1 };
    const uint32_t empty_mb[2] = { sb + MB_EMPTY0, sb + MB_EMPTY1 };

    const int tid    = threadIdx.x;
    const int lane   = tid & 31;
    const int warp   = tid >> 5;
    const int warp_m = warp >> 1;       // 0..3 (32 rows each)
    const int warp_n = warp & 1;        // 0..1 (64 cols each)

    const int start = (blockIdx.x * TOT_TILES) / GRID_SZ;
    const int end   = ((blockIdx.x + 1) * TOT_TILES) / GRID_SZ;
    int cur_qb = start >> 6;

    if (tid == 0) {
        mbar_init(full_mb[0], THREADS);  mbar_init(full_mb[1], THREADS);
        mbar_init(empty_mb[0], 8);       mbar_init(empty_mb[1], 8);
    }
    __syncthreads();

    // prologue: A(cur_qb) + B(kt(start)) -> buf0
    load_tile_async(As, g_Qn + (size_t)cur_qb * BM * D, tid);
    load_tile_async(Bs0, g_Kn + (size_t)(start & 63) * BN * D, tid);
    cp_mbar_arrive_noinc(full_mb[0]);

    // ldmatrix addresses (A smem location fixed; contents swap per qb)
    uint32_t a_base[2];
    #pragma unroll
    for (int mt = 0; mt < 2; ++mt)
        a_base[mt] = (uint32_t)__cvta_generic_to_shared(
            As + (warp_m * 32 + mt * 16 + (lane & 15)) * SPAD + (lane >> 4) * 8);
    uint32_t b_row_off[4];                // 4 x 16-col groups = 64 cols per warp
    #pragma unroll
    for (int b = 0; b < 4; ++b)
        b_row_off[b] = (uint32_t)(
            ((warp_n * 64 + b * 16 + ((lane >> 4) & 1) * 8 + (lane & 7)) * SPAD
             + ((lane >> 3) & 1) * 8) * sizeof(__nv_bfloat16));

    // parities: full waits start {0,0}; empty waits start {0,1}
    uint32_t cf0 = 0, cf1 = 0, pe0 = 0, pe1 = 1;

    float rsum[4]  = {0.f, 0.f, 0.f, 0.f};
    float rdiag[4] = {0.f, 0.f, 0.f, 0.f};

    // flush partials of qb via quad-shfl + global atomicAdd, then zero
    auto flush_partials = [&](int qb) {
        #pragma unroll
        for (int rs = 0; rs < 4; ++rs) {
            rsum[rs]  += __shfl_xor_sync(0xffffffffu, rsum[rs], 1);
            rsum[rs]  += __shfl_xor_sync(0xffffffffu, rsum[rs], 2);
            rdiag[rs] += __shfl_xor_sync(0xffffffffu, rdiag[rs], 1);
            rdiag[rs] += __shfl_xor_sync(0xffffffffu, rdiag[rs], 2);
        }
        if ((lane & 3) == 0) {
            #pragma unroll
            for (int rs = 0; rs < 4; ++rs) {
                int row = qb * BM + warp_m * 32 + (rs >> 1) * 16
                        + (rs & 1) * 8 + (lane >> 2);
                atomicAdd(&g_psum[row], rsum[rs]);
                atomicAdd(&g_pdiag[row], rdiag[rs]);
            }
        }
        #pragma unroll
        for (int rs = 0; rs < 4; ++rs) { rsum[rs] = 0.f; rdiag[rs] = 0.f; }
    };

    for (int t = start; t < end; ++t) {
        const int j  = t - start;
        const int qb = t >> 6;
        const int kt = t & 63;
        const int b  = j & 1;
        const int nb = b ^ 1;

        // qb transition (at most once per CTA): flush rows, reload A
        if (qb != cur_qb) {
            flush_partials(cur_qb);
            __syncthreads();     // all warps done with MMA on old A
            load_tile_async(As, g_Qn + (size_t)qb * BM * D, tid);
            cp_wait_all();       // A cps (+ any in-flight B(t) cps) complete
            __syncthreads();
            cur_qb = qb;
        }

        // producer: prefetch B of tile t+1 into buf nb
        if (t + 1 < end) {
            uint32_t pe = nb ? pe1 : pe0;
            mbar_wait(empty_mb[nb], pe);
            if (nb) pe1 ^= 1; else pe0 ^= 1;
            load_tile_async(Bbuf[nb],
                            g_Kn + (size_t)((t + 1) & 63) * BN * D, tid);
            cp_mbar_arrive_noinc(full_mb[nb]);
        }

        // consumer: tile t's B (and A) fully visible
        {
            uint32_t cf = b ? cf1 : cf0;
            mbar_wait(full_mb[b], cf);
            if (b) cf1 ^= 1; else cf0 ^= 1;
        }

        float acc[2][8][4];
        #pragma unroll
        for (int a = 0; a < 2; ++a)
            #pragma unroll
            for (int bb2 = 0; bb2 < 8; ++bb2)
                #pragma unroll
                for (int c = 0; c < 4; ++c) acc[a][bb2][c] = 0.f;

        const uint32_t bb = (uint32_t)__cvta_generic_to_shared(Bbuf[b]);

        #pragma unroll
        for (int ks = 0; ks < D / 16; ++ks) {
            uint32_t af[2][4], bf[16];
            ldsm_x4(af[0][0], af[0][1], af[0][2], af[0][3], a_base[0] + ks * 32);
            ldsm_x4(af[1][0], af[1][1], af[1][2], af[1][3], a_base[1] + ks * 32);
            #pragma unroll
            for (int g = 0; g < 4; ++g)
                ldsm_x4(bf[g * 4], bf[g * 4 + 1], bf[g * 4 + 2], bf[g * 4 + 3],
                        bb + b_row_off[g] + ks * 32);
            #pragma unroll
            for (int mt = 0; mt < 2; ++mt)
                #pragma unroll
                for (int nt = 0; nt < 8; ++nt) {
                    asm volatile(
                        "mma.sync.aligned.m16n8k16.row.col.f32.bf16.bf16.f32 "
                        "{%0,%1,%2,%3}, {%4,%5,%6,%7}, {%8,%9}, {%0,%1,%2,%3};\n"
                        : "+f"(acc[mt][nt][0]), "+f"(acc[mt][nt][1]),
                          "+f"(acc[mt][nt][2]), "+f"(acc[mt][nt][3])
                        : "r"(af[mt][0]), "r"(af[mt][1]),
                          "r"(af[mt][2]), "r"(af[mt][3]),
                          "r"(bf[nt * 2]), "r"(bf[nt * 2 + 1]));
                }
        }

        // done reading buf b -> producers may overwrite it (before epilogue)
        if (lane == 0) mbar_arrive(empty_mb[b]);

        // epilogue: f16x2 exp — 32 MUFU ops (2 exps each) + HADD2 trees.
        // Pair (c, c+1) shares a row -> same rsum bucket mt*2 + (c>>1).
        #pragma unroll
        for (int mt = 0; mt < 2; ++mt) {
            #pragma unroll
            for (int h = 0; h < 2; ++h) {
                uint32_t e[8];
                #pragma unroll
                for (int nt = 0; nt < 8; ++nt) {
                    uint32_t p;
                    asm("cvt.rn.f16x2.f32 %0, %1, %2;" : "=r"(p)
                        : "f"(acc[mt][nt][h * 2 + 1]), "f"(acc[mt][nt][h * 2]));
                    asm("ex2.approx.f16x2 %0, %1;" : "=r"(e[nt]) : "r"(p));
                }
                #pragma unroll
                for (int s = 4; s > 0; s >>= 1)
                    #pragma unroll
                    for (int i2 = 0; i2 < s; ++i2)
                        asm("add.rn.f16x2 %0, %1, %2;"
                            : "=r"(e[i2]) : "r"(e[i2]), "r"(e[i2 + s]));
                uint16_t lo16 = (uint16_t)(e[0] & 0xffffu);
                uint16_t hi16 = (uint16_t)(e[0] >> 16);
                float lo, hi;
                asm("cvt.f32.f16 %0, %1;" : "=f"(lo) : "h"(lo16));
                asm("cvt.f32.f16 %0, %1;" : "=f"(hi) : "h"(hi16));
                rsum[mt * 2 + h] += lo + hi;
            }
        }

        // diagonal lives exactly in the kt == qb tile (exact f32 path)
        if (kt == qb) {
            #pragma unroll
            for (int mt = 0; mt < 2; ++mt)
                #pragma unroll
                for (int nt = 0; nt < 8; ++nt)
                    #pragma unroll
                    for (int c = 0; c < 4; ++c) {
                        int lr = warp_m * 32 + mt * 16 + (c >> 1) * 8 + (lane >> 2);
                        int lc = warp_n * 64 + nt * 8 + (lane & 3) * 2 + (c & 1);
                        if (lr == lc) rdiag[mt * 2 + (c >> 1)] += acc[mt][nt][c];
                    }
        }
    }

    flush_partials(cur_qb);
}

// ---------------------------------------------------------------------------
// Kernel 3: finalize. loss = mean( ln2 * (log2(rowsum) - diag_log2) )
// ---------------------------------------------------------------------------
__global__ void finalize_kernel(float* __restrict__ out) {
    __shared__ float wsum[8];
    float acc = 0.f;
    for (int r = blockIdx.x * 256 + threadIdx.x; r < NMAX; r += gridDim.x * 256)
        acc += LN2 * (log2f(g_psum[r]) - g_pdiag[r]);
    #pragma unroll
    for (int o = 16; o > 0; o >>= 1) acc += __shfl_xor_sync(0xffffffffu, acc, o);
    if ((threadIdx.x & 31) == 0) wsum[threadIdx.x >> 5] = acc;
    __syncthreads();
    if (threadIdx.x == 0) {
        float t = 0.f;
        #pragma unroll
        for (int i = 0; i < 8; ++i) t += wsum[i];
        atomicAdd(out, t / (float)NMAX);
    }
}

// ---------------------------------------------------------------------------
extern "C" void kernel_launch(void* const* d_in, const int* in_sizes, int n_in,
                              void* d_out, int out_size) {
    const float* q = (const float*)d_in[0];
    const float* k = (const float*)d_in[1];
    const int N = in_sizes[0] / D;          // 8192
    float* out = (float*)d_out;

    normalize_kernel<<<2 * N / 16, 256>>>(q, k, N);

    size_t smem = DATA_OFF + (size_t)(BM + 2 * BN) * SPAD * sizeof(__nv_bfloat16);
    cudaFuncSetAttribute(infonce_kernel,
                         cudaFuncAttributeMaxDynamicSharedMemorySize, (int)smem);
    infonce_kernel<<<GRID_SZ, THREADS, smem>>>();

    cudaMemsetAsync(out, 0, sizeof(float), 0);   // zero atomicAdd accumulator

    finalize_kernel<<<16, 256>>>(out);
}

// round 14
// speedup vs baseline: 1.0373x; 1.0373x over previous
#include <cuda_runtime.h>
#include <cuda_fp16.h>
#include <cstdint>

#define D        256
#define NMAX     8192
#define BM       128
#define BN       128
#define QBLKS    (NMAX / BM)             // 64
#define KTILES   (NMAX / BN)             // 64
#define TOT_TILES (QBLKS * KTILES)       // 4096
#define GRID_SZ  148                     // one CTA per SM, balanced static ranges
#define THREADS  256                     // 8 warps, warp grid 4(M) x 2(N)
#define SPAD     264                     // 256 + 8 halves pad: conflict-free LDSM

#define LOG2E    1.4426950408889634f
#define LN2      0.6931471805599453f

// smem: [0..31] mbarriers (full0, full1, empty0, empty1), data from 128
#define MB_FULL0   0
#define MB_FULL1   8
#define MB_EMPTY0  16
#define MB_EMPTY1  24
#define DATA_OFF   128

__device__ __align__(16) __half g_Qn[(size_t)NMAX * D];
__device__ __align__(16) __half g_Kn[(size_t)NMAX * D];
__device__ float g_psum[NMAX];
__device__ float g_pdiag[NMAX];

// ---------------- helpers ----------------
__device__ __forceinline__ void cp_async16(void* smem_dst, const void* gmem_src) {
    uint32_t s = (uint32_t)__cvta_generic_to_shared(smem_dst);
    asm volatile("cp.async.cg.shared.global [%0], [%1], 16;\n" :: "r"(s), "l"(gmem_src));
}
// .noinc: one REAL arrival per thread (init count == #threads).
__device__ __forceinline__ void cp_mbar_arrive_noinc(uint32_t mbar) {
    asm volatile("cp.async.mbarrier.arrive.noinc.shared::cta.b64 [%0];"
                 :: "r"(mbar) : "memory");
}
__device__ __forceinline__ void cp_wait_all() {
    asm volatile("cp.async.wait_group 0;\n" ::: "memory");
}
__device__ __forceinline__ void mbar_init(uint32_t a, uint32_t cnt) {
    asm volatile("mbarrier.init.shared.b64 [%0], %1;" :: "r"(a), "r"(cnt) : "memory");
}
__device__ __forceinline__ void mbar_arrive(uint32_t a) {
    asm volatile("mbarrier.arrive.shared.b64 _, [%0];" :: "r"(a) : "memory");
}
__device__ __forceinline__ void mbar_wait(uint32_t a, uint32_t parity) {
    asm volatile("{\n\t.reg .pred P1;\n\t"
                 "WAIT_LOOP_%=:\n\t"
                 "mbarrier.try_wait.parity.acquire.cta.shared::cta.b64 P1, [%0], %1, 0x989680;\n\t"
                 "@P1 bra.uni WAIT_DONE_%=;\n\t"
                 "bra.uni WAIT_LOOP_%=;\n\t"
                 "WAIT_DONE_%=:\n\t}" :: "r"(a), "r"(parity) : "memory");
}
__device__ __forceinline__ void ldsm_x4(uint32_t& r0, uint32_t& r1,
                                        uint32_t& r2, uint32_t& r3, uint32_t addr) {
    asm volatile("ldmatrix.sync.aligned.m8n8.x4.shared.b16 {%0,%1,%2,%3}, [%4];"
                 : "=r"(r0), "=r"(r1), "=r"(r2), "=r"(r3) : "r"(addr));
}

// Load one [128 x 256 f16] tile into SPAD-padded smem via cp.async (256 thr).
__device__ __forceinline__ void load_tile_async(__half* s,
                                                const __half* g, int tid) {
    const uint4* src = (const uint4*)g;
    #pragma unroll
    for (int i = tid; i < BM * 32; i += THREADS) {   // 32 x 16B chunks per row
        int r = i >> 5, c = i & 31;
        cp_async16(s + r * SPAD + c * 8, src + r * 32 + c);
    }
}

// ---------------------------------------------------------------------------
// Kernel 1: L2 normalize (one warp per TWO rows) + zero the partial arrays.
// Queries get 2*log2(e) folded in -> log2-domain logits, no max needed.
// Output in f16 (more mantissa than bf16; range needed <= 4).
// ---------------------------------------------------------------------------
__global__ void normalize_kernel(const float* __restrict__ q,
                                 const float* __restrict__ k, int N) {
    // zero partial accumulators (ordering: same stream, before infonce)
    int gid = blockIdx.x * 256 + threadIdx.x;
    if (gid < NMAX) { g_psum[gid] = 0.f; g_pdiag[gid] = 0.f; }

    const int warp = threadIdx.x >> 5, lane = threadIdx.x & 31;
    const int row0 = blockIdx.x * 16 + warp * 2;     // grid = 2N/16
    const bool is_q = row0 < N;
    const int  r0   = is_q ? row0 : row0 - N;
    const float* srcb = is_q ? q : k;
    __half* dstb = is_q ? g_Qn : g_Kn;

    const float4* sA = (const float4*)(srcb + (size_t)r0 * D);
    const float4* sB = (const float4*)(srcb + (size_t)(r0 + 1) * D);
    float4 a0 = sA[lane * 2], a1 = sA[lane * 2 + 1];
    float4 b0 = sB[lane * 2], b1 = sB[lane * 2 + 1];

    float ssA = a0.x*a0.x + a0.y*a0.y + a0.z*a0.z + a0.w*a0.w
              + a1.x*a1.x + a1.y*a1.y + a1.z*a1.z + a1.w*a1.w;
    float ssB = b0.x*b0.x + b0.y*b0.y + b0.z*b0.z + b0.w*b0.w
              + b1.x*b1.x + b1.y*b1.y + b1.z*b1.z + b1.w*b1.w;
    #pragma unroll
    for (int o = 16; o > 0; o >>= 1) {
        ssA += __shfl_xor_sync(0xffffffffu, ssA, o);
        ssB += __shfl_xor_sync(0xffffffffu, ssB, o);
    }

    float scA = rsqrtf(fmaxf(ssA, 1e-24f));
    float scB = rsqrtf(fmaxf(ssB, 1e-24f));
    if (is_q) { scA *= 2.0f * LOG2E; scB *= 2.0f * LOG2E; }

    uint4 oA, oB;
    {
        __half2 t0 = __float22half2_rn({a0.x*scA, a0.y*scA});
        __half2 t1 = __float22half2_rn({a0.z*scA, a0.w*scA});
        __half2 t2 = __float22half2_rn({a1.x*scA, a1.y*scA});
        __half2 t3 = __float22half2_rn({a1.z*scA, a1.w*scA});
        oA.x = *(uint32_t*)&t0; oA.y = *(uint32_t*)&t1;
        oA.z = *(uint32_t*)&t2; oA.w = *(uint32_t*)&t3;
    }
    {
        __half2 t0 = __float22half2_rn({b0.x*scB, b0.y*scB});
        __half2 t1 = __float22half2_rn({b0.z*scB, b0.w*scB});
        __half2 t2 = __float22half2_rn({b1.x*scB, b1.y*scB});
        __half2 t3 = __float22half2_rn({b1.z*scB, b1.w*scB});
        oB.x = *(uint32_t*)&t0; oB.y = *(uint32_t*)&t1;
        oB.z = *(uint32_t*)&t2; oB.w = *(uint32_t*)&t3;
    }
    ((uint4*)(dstb + (size_t)r0 * D))[lane]       = oA;
    ((uint4*)(dstb + (size_t)(r0 + 1) * D))[lane] = oB;
}

// ---------------------------------------------------------------------------
// Kernel 2: f16 mma.sync (f16 accumulate!) GEMM + fused sum(2^logit).
// 148 CTAs, balanced static tile ranges (R12 structure). Accumulators are
// f16x2 pairs -> ex2.approx.f16x2 directly, NO conversion tax (R13's flaw).
// ---------------------------------------------------------------------------
__global__ __launch_bounds__(THREADS, 1)
void infonce_kernel() {
    extern __shared__ __align__(16) char smem_raw[];
    const uint32_t sb = (uint32_t)__cvta_generic_to_shared(smem_raw);
    __half* As  = (__half*)(smem_raw + DATA_OFF);    // 128 * SPAD
    __half* Bs0 = As + BM * SPAD;                    // buf 0
    __half* Bs1 = Bs0 + BN * SPAD;                   // buf 1
    __half* Bbuf[2] = { Bs0, Bs1 };

    const uint32_t full_mb[2]  = { sb + MB_FULL0,  sb + MB_FULL1 };
    const uint32_t empty_mb[2] = { sb + MB_EMPTY0, sb + MB_EMPTY1 };

    const int tid    = threadIdx.x;
    const int lane   = tid & 31;
    const int warp   = tid >> 5;
    const int warp_m = warp >> 1;       // 0..3 (32 rows each)
    const int warp_n = warp & 1;        // 0..1 (64 cols each)

    const int start = (blockIdx.x * TOT_TILES) / GRID_SZ;
    const int end   = ((blockIdx.x + 1) * TOT_TILES) / GRID_SZ;
    int cur_qb = start >> 6;

    if (tid == 0) {
        mbar_init(full_mb[0], THREADS);  mbar_init(full_mb[1], THREADS);
        mbar_init(empty_mb[0], 8);       mbar_init(empty_mb[1], 8);
    }
    __syncthreads();

    // prologue: A(cur_qb) + B(kt(start)) -> buf0
    load_tile_async(As, g_Qn + (size_t)cur_qb * BM * D, tid);
    load_tile_async(Bs0, g_Kn + (size_t)(start & 63) * BN * D, tid);
    cp_mbar_arrive_noinc(full_mb[0]);

    // ldmatrix addresses (A smem location fixed; contents swap per qb)
    uint32_t a_base[2];
    #pragma unroll
    for (int mt = 0; mt < 2; ++mt)
        a_base[mt] = (uint32_t)__cvta_generic_to_shared(
            As + (warp_m * 32 + mt * 16 + (lane & 15)) * SPAD + (lane >> 4) * 8);
    uint32_t b_row_off[4];                // 4 x 16-col groups = 64 cols per warp
    #pragma unroll
    for (int b = 0; b < 4; ++b)
        b_row_off[b] = (uint32_t)(
            ((warp_n * 64 + b * 16 + ((lane >> 4) & 1) * 8 + (lane & 7)) * SPAD
             + ((lane >> 3) & 1) * 8) * sizeof(__half));

    // parities: full waits start {0,0}; empty waits start {0,1}
    uint32_t cf0 = 0, cf1 = 0, pe0 = 0, pe1 = 1;

    float rsum[4]  = {0.f, 0.f, 0.f, 0.f};
    float rdiag[4] = {0.f, 0.f, 0.f, 0.f};

    // flush partials of qb via quad-shfl + global atomicAdd, then zero
    auto flush_partials = [&](int qb) {
        #pragma unroll
        for (int rs = 0; rs < 4; ++rs) {
            rsum[rs]  += __shfl_xor_sync(0xffffffffu, rsum[rs], 1);
            rsum[rs]  += __shfl_xor_sync(0xffffffffu, rsum[rs], 2);
            rdiag[rs] += __shfl_xor_sync(0xffffffffu, rdiag[rs], 1);
            rdiag[rs] += __shfl_xor_sync(0xffffffffu, rdiag[rs], 2);
        }
        if ((lane & 3) == 0) {
            #pragma unroll
            for (int rs = 0; rs < 4; ++rs) {
                int row = qb * BM + warp_m * 32 + (rs >> 1) * 16
                        + (rs & 1) * 8 + (lane >> 2);
                atomicAdd(&g_psum[row], rsum[rs]);
                atomicAdd(&g_pdiag[row], rdiag[rs]);
            }
        }
        #pragma unroll
        for (int rs = 0; rs < 4; ++rs) { rsum[rs] = 0.f; rdiag[rs] = 0.f; }
    };

    for (int t = start; t < end; ++t) {
        const int j  = t - start;
        const int qb = t >> 6;
        const int kt = t & 63;
        const int b  = j & 1;
        const int nb = b ^ 1;

        // qb transition (at most once per CTA): flush rows, reload A
        if (qb != cur_qb) {
            flush_partials(cur_qb);
            __syncthreads();     // all warps done with MMA on old A
            load_tile_async(As, g_Qn + (size_t)qb * BM * D, tid);
            cp_wait_all();       // A cps (+ any in-flight B(t) cps) complete
            __syncthreads();
            cur_qb = qb;
        }

        // producer: prefetch B of tile t+1 into buf nb
        if (t + 1 < end) {
            uint32_t pe = nb ? pe1 : pe0;
            mbar_wait(empty_mb[nb], pe);
            if (nb) pe1 ^= 1; else pe0 ^= 1;
            load_tile_async(Bbuf[nb],
                            g_Kn + (size_t)((t + 1) & 63) * BN * D, tid);
            cp_mbar_arrive_noinc(full_mb[nb]);
        }

        // consumer: tile t's B (and A) fully visible
        {
            uint32_t cf = b ? cf1 : cf0;
            mbar_wait(full_mb[b], cf);
            if (b) cf1 ^= 1; else cf0 ^= 1;
        }

        // f16 accumulators: acc[mt][nt][0]={c0,c1} (row r), [1]={c2,c3} (row r+8)
        uint32_t acc[2][8][2];
        #pragma unroll
        for (int a = 0; a < 2; ++a)
            #pragma unroll
            for (int bb2 = 0; bb2 < 8; ++bb2) { acc[a][bb2][0] = 0; acc[a][bb2][1] = 0; }

        const uint32_t bb = (uint32_t)__cvta_generic_to_shared(Bbuf[b]);

        #pragma unroll
        for (int ks = 0; ks < D / 16; ++ks) {
            uint32_t af[2][4], bf[16];
            ldsm_x4(af[0][0], af[0][1], af[0][2], af[0][3], a_base[0] + ks * 32);
            ldsm_x4(af[1][0], af[1][1], af[1][2], af[1][3], a_base[1] + ks * 32);
            #pragma unroll
            for (int g = 0; g < 4; ++g)
                ldsm_x4(bf[g * 4], bf[g * 4 + 1], bf[g * 4 + 2], bf[g * 4 + 3],
                        bb + b_row_off[g] + ks * 32);
            #pragma unroll
            for (int mt = 0; mt < 2; ++mt)
                #pragma unroll
                for (int nt = 0; nt < 8; ++nt) {
                    asm volatile(
                        "mma.sync.aligned.m16n8k16.row.col.f16.f16.f16.f16 "
                        "{%0,%1}, {%2,%3,%4,%5}, {%6,%7}, {%0,%1};\n"
                        : "+r"(acc[mt][nt][0]), "+r"(acc[mt][nt][1])
                        : "r"(af[mt][0]), "r"(af[mt][1]),
                          "r"(af[mt][2]), "r"(af[mt][3]),
                          "r"(bf[nt * 2]), "r"(bf[nt * 2 + 1]));
                }
        }

        // done reading buf b -> producers may overwrite it (before epilogue)
        if (lane == 0) mbar_arrive(empty_mb[b]);

        // epilogue: accumulators are ALREADY f16x2 -> 32 ex2.approx.f16x2
        // (2 exps each) + HADD2 trees; no conversion tax.
        #pragma unroll
        for (int mt = 0; mt < 2; ++mt) {
            #pragma unroll
            for (int rh = 0; rh < 2; ++rh) {       // row-half: c01 / c23
                uint32_t e[8];
                #pragma unroll
                for (int nt = 0; nt < 8; ++nt)
                    asm("ex2.approx.f16x2 %0, %1;" : "=r"(e[nt])
                        : "r"(acc[mt][nt][rh]));
                #pragma unroll
                for (int s = 4; s > 0; s >>= 1)    // tree sum <= 59, no overflow
                    #pragma unroll
                    for (int i2 = 0; i2 < s; ++i2)
                        asm("add.rn.f16x2 %0, %1, %2;"
                            : "=r"(e[i2]) : "r"(e[i2]), "r"(e[i2 + s]));
                uint16_t lo16 = (uint16_t)(e[0] & 0xffffu);
                uint16_t hi16 = (uint16_t)(e[0] >> 16);
                float lo, hi;
                asm("cvt.f32.f16 %0, %1;" : "=f"(lo) : "h"(lo16));
                asm("cvt.f32.f16 %0, %1;" : "=f"(hi) : "h"(hi16));
                rsum[mt * 2 + rh] += lo + hi;
            }
        }

        // diagonal lives exactly in the kt == qb tile
        if (kt == qb) {
            #pragma unroll
            for (int mt = 0; mt < 2; ++mt)
                #pragma unroll
                for (int nt = 0; nt < 8; ++nt)
                    #pragma unroll
                    for (int c = 0; c < 4; ++c) {
                        int lr = warp_m * 32 + mt * 16 + (c >> 1) * 8 + (lane >> 2);
                        int lc = warp_n * 64 + nt * 8 + (lane & 3) * 2 + (c & 1);
                        if (lr == lc) {
                            uint32_t reg = acc[mt][nt][c >> 1];
                            uint16_t hbits = (c & 1) ? (uint16_t)(reg >> 16)
                                                     : (uint16_t)(reg & 0xffffu);
                            float v;
                            asm("cvt.f32.f16 %0, %1;" : "=f"(v) : "h"(hbits));
                            rdiag[mt * 2 + (c >> 1)] += v;
                        }
                    }
        }
    }

    flush_partials(cur_qb);
}

// ---------------------------------------------------------------------------
// Kernel 3: finalize. loss = mean( ln2 * (log2(rowsum) - diag_log2) )
// ---------------------------------------------------------------------------
__global__ void finalize_kernel(float* __restrict__ out) {
    __shared__ float wsum[8];
    float acc = 0.f;
    for (int r = blockIdx.x * 256 + threadIdx.x; r < NMAX; r += gridDim.x * 256)
        acc += LN2 * (log2f(g_psum[r]) - g_pdiag[r]);
    #pragma unroll
    for (int o = 16; o > 0; o >>= 1) acc += __shfl_xor_sync(0xffffffffu, acc, o);
    if ((threadIdx.x & 31) == 0) wsum[threadIdx.x >> 5] = acc;
    __syncthreads();
    if (threadIdx.x == 0) {
        float t = 0.f;
        #pragma unroll
        for (int i = 0; i < 8; ++i) t += wsum[i];
        atomicAdd(out, t / (float)NMAX);
    }
}

// ---------------------------------------------------------------------------
extern "C" void kernel_launch(void* const* d_in, const int* in_sizes, int n_in,
                              void* d_out, int out_size) {
    const float* q = (const float*)d_in[0];
    const float* k = (const float*)d_in[1];
    const int N = in_sizes[0] / D;          // 8192
    float* out = (float*)d_out;

    normalize_kernel<<<2 * N / 16, 256>>>(q, k, N);

    size_t smem = DATA_OFF + (size_t)(BM + 2 * BN) * SPAD * sizeof(__half);
    cudaFuncSetAttribute(infonce_kernel,
                         cudaFuncAttributeMaxDynamicSharedMemorySize, (int)smem);
    infonce_kernel<<<GRID_SZ, THREADS, smem>>>();

    cudaMemsetAsync(out, 0, sizeof(float), 0);   // zero atomicAdd accumulator

    finalize_kernel<<<16, 256>>>(out);
}

// round 15
// speedup vs baseline: 1.1424x; 1.1013x over previous
#include <cuda_runtime.h>
#include <cuda_bf16.h>
#include <cstdint>

#define D        256
#define NMAX     8192
#define BM       128
#define BN       128
#define QBLKS    (NMAX / BM)             // 64
#define KTILES   (NMAX / BN)             // 64
#define TOT_TILES (QBLKS * KTILES)       // 4096
#define GRID_SZ  148                     // one CTA per SM, balanced static ranges
#define THREADS  256                     // 8 warps, warp grid 4(M) x 2(N)
#define SPAD     264                     // 256 + 8 halves pad: conflict-free LDSM

#define LOG2E    1.4426950408889634f
#define LN2      0.6931471805599453f

// smem: [0..31] mbarriers (full0, full1, empty0, empty1), data from 128
#define MB_FULL0   0
#define MB_FULL1   8
#define MB_EMPTY0  16
#define MB_EMPTY1  24
#define DATA_OFF   128

__device__ __align__(16) __nv_bfloat16 g_Qn[(size_t)NMAX * D];
__device__ __align__(16) __nv_bfloat16 g_Kn[(size_t)NMAX * D];
__device__ float g_psum[NMAX];
__device__ float g_pdiag[NMAX];
__device__ unsigned int g_done_ctr;      // zero-initialized; reset by last CTA

// ---------------- helpers ----------------
__device__ __forceinline__ void cp_async16(void* smem_dst, const void* gmem_src) {
    uint32_t s = (uint32_t)__cvta_generic_to_shared(smem_dst);
    asm volatile("cp.async.cg.shared.global [%0], [%1], 16;\n" :: "r"(s), "l"(gmem_src));
}
// .noinc: one REAL arrival per thread (init count == #threads).
__device__ __forceinline__ void cp_mbar_arrive_noinc(uint32_t mbar) {
    asm volatile("cp.async.mbarrier.arrive.noinc.shared::cta.b64 [%0];"
                 :: "r"(mbar) : "memory");
}
__device__ __forceinline__ void cp_wait_all() {
    asm volatile("cp.async.wait_group 0;\n" ::: "memory");
}
__device__ __forceinline__ void mbar_init(uint32_t a, uint32_t cnt) {
    asm volatile("mbarrier.init.shared.b64 [%0], %1;" :: "r"(a), "r"(cnt) : "memory");
}
__device__ __forceinline__ void mbar_arrive(uint32_t a) {
    asm volatile("mbarrier.arrive.shared.b64 _, [%0];" :: "r"(a) : "memory");
}
__device__ __forceinline__ void mbar_wait(uint32_t a, uint32_t parity) {
    asm volatile("{\n\t.reg .pred P1;\n\t"
                 "WAIT_LOOP_%=:\n\t"
                 "mbarrier.try_wait.parity.acquire.cta.shared::cta.b64 P1, [%0], %1, 0x989680;\n\t"
                 "@P1 bra.uni WAIT_DONE_%=;\n\t"
                 "bra.uni WAIT_LOOP_%=;\n\t"
                 "WAIT_DONE_%=:\n\t}" :: "r"(a), "r"(parity) : "memory");
}
__device__ __forceinline__ void ldsm_x4(uint32_t& r0, uint32_t& r1,
                                        uint32_t& r2, uint32_t& r3, uint32_t addr) {
    asm volatile("ldmatrix.sync.aligned.m8n8.x4.shared.b16 {%0,%1,%2,%3}, [%4];"
                 : "=r"(r0), "=r"(r1), "=r"(r2), "=r"(r3) : "r"(addr));
}
__device__ __forceinline__ float exp2_fast(float x) {
    float r;
    asm("ex2.approx.ftz.f32 %0, %1;" : "=f"(r) : "f"(x));
    return r;
}

// Load one [128 x 256 bf16] tile into SPAD-padded smem via cp.async (256 thr).
__device__ __forceinline__ void load_tile_async(__nv_bfloat16* s,
                                                const __nv_bfloat16* g, int tid) {
    const uint4* src = (const uint4*)g;
    #pragma unroll
    for (int i = tid; i < BM * 32; i += THREADS) {   // 32 x 16B chunks per row
        int r = i >> 5, c = i & 31;
        cp_async16(s + r * SPAD + c * 8, src + r * 32 + c);
    }
}

// ---------------------------------------------------------------------------
// Kernel 1: L2 normalize (one warp per TWO rows) + zero the partial arrays.
// Queries get 2*log2(e) folded in -> log2-domain logits, no max needed.
// ---------------------------------------------------------------------------
__global__ void normalize_kernel(const float* __restrict__ q,
                                 const float* __restrict__ k, int N) {
    // zero partial accumulators (ordering: same stream, before infonce)
    int gid = blockIdx.x * 256 + threadIdx.x;
    if (gid < NMAX) { g_psum[gid] = 0.f; g_pdiag[gid] = 0.f; }

    const int warp = threadIdx.x >> 5, lane = threadIdx.x & 31;
    const int row0 = blockIdx.x * 16 + warp * 2;     // grid = 2N/16
    const bool is_q = row0 < N;
    const int  r0   = is_q ? row0 : row0 - N;
    const float* srcb = is_q ? q : k;
    __nv_bfloat16* dstb = is_q ? g_Qn : g_Kn;

    const float4* sA = (const float4*)(srcb + (size_t)r0 * D);
    const float4* sB = (const float4*)(srcb + (size_t)(r0 + 1) * D);
    float4 a0 = sA[lane * 2], a1 = sA[lane * 2 + 1];
    float4 b0 = sB[lane * 2], b1 = sB[lane * 2 + 1];

    float ssA = a0.x*a0.x + a0.y*a0.y + a0.z*a0.z + a0.w*a0.w
              + a1.x*a1.x + a1.y*a1.y + a1.z*a1.z + a1.w*a1.w;
    float ssB = b0.x*b0.x + b0.y*b0.y + b0.z*b0.z + b0.w*b0.w
              + b1.x*b1.x + b1.y*b1.y + b1.z*b1.z + b1.w*b1.w;
    #pragma unroll
    for (int o = 16; o > 0; o >>= 1) {
        ssA += __shfl_xor_sync(0xffffffffu, ssA, o);
        ssB += __shfl_xor_sync(0xffffffffu, ssB, o);
    }

    float scA = rsqrtf(fmaxf(ssA, 1e-24f));
    float scB = rsqrtf(fmaxf(ssB, 1e-24f));
    if (is_q) { scA *= 2.0f * LOG2E; scB *= 2.0f * LOG2E; }

    uint4 oA, oB;
    {
        __nv_bfloat162 t0 = __float22bfloat162_rn({a0.x*scA, a0.y*scA});
        __nv_bfloat162 t1 = __float22bfloat162_rn({a0.z*scA, a0.w*scA});
        __nv_bfloat162 t2 = __float22bfloat162_rn({a1.x*scA, a1.y*scA});
        __nv_bfloat162 t3 = __float22bfloat162_rn({a1.z*scA, a1.w*scA});
        oA.x = *(uint32_t*)&t0; oA.y = *(uint32_t*)&t1;
        oA.z = *(uint32_t*)&t2; oA.w = *(uint32_t*)&t3;
    }
    {
        __nv_bfloat162 t0 = __float22bfloat162_rn({b0.x*scB, b0.y*scB});
        __nv_bfloat162 t1 = __float22bfloat162_rn({b0.z*scB, b0.w*scB});
        __nv_bfloat162 t2 = __float22bfloat162_rn({b1.x*scB, b1.y*scB});
        __nv_bfloat162 t3 = __float22bfloat162_rn({b1.z*scB, b1.w*scB});
        oB.x = *(uint32_t*)&t0; oB.y = *(uint32_t*)&t1;
        oB.z = *(uint32_t*)&t2; oB.w = *(uint32_t*)&t3;
    }
    ((uint4*)(dstb + (size_t)r0 * D))[lane]       = oA;
    ((uint4*)(dstb + (size_t)(r0 + 1) * D))[lane] = oB;
}

// ---------------------------------------------------------------------------
// Kernel 2: bf16 mma.sync GEMM + fused sum(2^logit) + fused finalize.
// 148 CTAs; CTA i owns unit tiles [i*4096/148, (i+1)*4096/148) qb-major
// (27-28 tiles, balanced; <=1 A-reload per CTA). R12 mainloop verbatim.
// Last CTA to finish computes the mean loss and writes out[0] directly
// (threadfence + counter), eliminating the memset + finalize launches.
// ---------------------------------------------------------------------------
__global__ __launch_bounds__(THREADS, 1)
void infonce_kernel(float* __restrict__ out) {
    extern __shared__ __align__(16) char smem_raw[];
    const uint32_t sb = (uint32_t)__cvta_generic_to_shared(smem_raw);
    __nv_bfloat16* As  = (__nv_bfloat16*)(smem_raw + DATA_OFF); // 128 * SPAD
    __nv_bfloat16* Bs0 = As + BM * SPAD;                        // buf 0
    __nv_bfloat16* Bs1 = Bs0 + BN * SPAD;                       // buf 1
    __nv_bfloat16* Bbuf[2] = { Bs0, Bs1 };

    const uint32_t full_mb[2]  = { sb + MB_FULL0,  sb + MB_FULL1 };
    const uint32_t empty_mb[2] = { sb + MB_EMPTY0, sb + MB_EMPTY1 };

    const int tid    = threadIdx.x;
    const int lane   = tid & 31;
    const int warp   = tid >> 5;
    const int warp_m = warp >> 1;       // 0..3 (32 rows each)
    const int warp_n = warp & 1;        // 0..1 (64 cols each)

    const int start = (blockIdx.x * TOT_TILES) / GRID_SZ;
    const int end   = ((blockIdx.x + 1) * TOT_TILES) / GRID_SZ;
    int cur_qb = start >> 6;

    if (tid == 0) {
        mbar_init(full_mb[0], THREADS);  mbar_init(full_mb[1], THREADS);
        mbar_init(empty_mb[0], 8);       mbar_init(empty_mb[1], 8);
    }
    __syncthreads();

    // prologue: A(cur_qb) + B(kt(start)) -> buf0
    load_tile_async(As, g_Qn + (size_t)cur_qb * BM * D, tid);
    load_tile_async(Bs0, g_Kn + (size_t)(start & 63) * BN * D, tid);
    cp_mbar_arrive_noinc(full_mb[0]);

    // ldmatrix addresses (A smem location fixed; contents swap per qb)
    uint32_t a_base[2];
    #pragma unroll
    for (int mt = 0; mt < 2; ++mt)
        a_base[mt] = (uint32_t)__cvta_generic_to_shared(
            As + (warp_m * 32 + mt * 16 + (lane & 15)) * SPAD + (lane >> 4) * 8);
    uint32_t b_row_off[4];                // 4 x 16-col groups = 64 cols per warp
    #pragma unroll
    for (int b = 0; b < 4; ++b)
        b_row_off[b] = (uint32_t)(
            ((warp_n * 64 + b * 16 + ((lane >> 4) & 1) * 8 + (lane & 7)) * SPAD
             + ((lane >> 3) & 1) * 8) * sizeof(__nv_bfloat16));

    // parities: full waits start {0,0}; empty waits start {0,1}
    uint32_t cf0 = 0, cf1 = 0, pe0 = 0, pe1 = 1;

    float rsum[4]  = {0.f, 0.f, 0.f, 0.f};
    float rdiag[4] = {0.f, 0.f, 0.f, 0.f};

    // flush partials of qb via quad-shfl + global atomicAdd, then zero
    auto flush_partials = [&](int qb) {
        #pragma unroll
        for (int rs = 0; rs < 4; ++rs) {
            rsum[rs]  += __shfl_xor_sync(0xffffffffu, rsum[rs], 1);
            rsum[rs]  += __shfl_xor_sync(0xffffffffu, rsum[rs], 2);
            rdiag[rs] += __shfl_xor_sync(0xffffffffu, rdiag[rs], 1);
            rdiag[rs] += __shfl_xor_sync(0xffffffffu, rdiag[rs], 2);
        }
        if ((lane & 3) == 0) {
            #pragma unroll
            for (int rs = 0; rs < 4; ++rs) {
                int row = qb * BM + warp_m * 32 + (rs >> 1) * 16
                        + (rs & 1) * 8 + (lane >> 2);
                atomicAdd(&g_psum[row], rsum[rs]);
                atomicAdd(&g_pdiag[row], rdiag[rs]);
            }
        }
        #pragma unroll
        for (int rs = 0; rs < 4; ++rs) { rsum[rs] = 0.f; rdiag[rs] = 0.f; }
    };

    for (int t = start; t < end; ++t) {
        const int j  = t - start;
        const int qb = t >> 6;
        const int kt = t & 63;
        const int b  = j & 1;
        const int nb = b ^ 1;

        // qb transition (at most once per CTA): flush rows, reload A
        if (qb != cur_qb) {
            flush_partials(cur_qb);
            __syncthreads();     // all warps done with MMA on old A
            load_tile_async(As, g_Qn + (size_t)qb * BM * D, tid);
            cp_wait_all();       // A cps (+ any in-flight B(t) cps) complete
            __syncthreads();
            cur_qb = qb;
        }

        // producer: prefetch B of tile t+1 into buf nb
        if (t + 1 < end) {
            uint32_t pe = nb ? pe1 : pe0;
            mbar_wait(empty_mb[nb], pe);
            if (nb) pe1 ^= 1; else pe0 ^= 1;
            load_tile_async(Bbuf[nb],
                            g_Kn + (size_t)((t + 1) & 63) * BN * D, tid);
            cp_mbar_arrive_noinc(full_mb[nb]);
        }

        // consumer: tile t's B (and A) fully visible
        {
            uint32_t cf = b ? cf1 : cf0;
            mbar_wait(full_mb[b], cf);
            if (b) cf1 ^= 1; else cf0 ^= 1;
        }

        float acc[2][8][4];
        #pragma unroll
        for (int a = 0; a < 2; ++a)
            #pragma unroll
            for (int bb2 = 0; bb2 < 8; ++bb2)
                #pragma unroll
                for (int c = 0; c < 4; ++c) acc[a][bb2][c] = 0.f;

        const uint32_t bb = (uint32_t)__cvta_generic_to_shared(Bbuf[b]);

        #pragma unroll
        for (int ks = 0; ks < D / 16; ++ks) {
            uint32_t af[2][4], bf[16];
            ldsm_x4(af[0][0], af[0][1], af[0][2], af[0][3], a_base[0] + ks * 32);
            ldsm_x4(af[1][0], af[1][1], af[1][2], af[1][3], a_base[1] + ks * 32);
            #pragma unroll
            for (int g = 0; g < 4; ++g)
                ldsm_x4(bf[g * 4], bf[g * 4 + 1], bf[g * 4 + 2], bf[g * 4 + 3],
                        bb + b_row_off[g] + ks * 32);
            #pragma unroll
            for (int mt = 0; mt < 2; ++mt)
                #pragma unroll
                for (int nt = 0; nt < 8; ++nt) {
                    asm volatile(
                        "mma.sync.aligned.m16n8k16.row.col.f32.bf16.bf16.f32 "
                        "{%0,%1,%2,%3}, {%4,%5,%6,%7}, {%8,%9}, {%0,%1,%2,%3};\n"
                        : "+f"(acc[mt][nt][0]), "+f"(acc[mt][nt][1]),
                          "+f"(acc[mt][nt][2]), "+f"(acc[mt][nt][3])
                        : "r"(af[mt][0]), "r"(af[mt][1]),
                          "r"(af[mt][2]), "r"(af[mt][3]),
                          "r"(bf[nt * 2]), "r"(bf[nt * 2 + 1]));
                }
        }

        // done reading buf b -> producers may overwrite it (before epilogue)
        if (lane == 0) mbar_arrive(empty_mb[b]);

        // epilogue: 64 ex2 + adds (no max needed in log2 domain)
        #pragma unroll
        for (int mt = 0; mt < 2; ++mt)
            #pragma unroll
            for (int nt = 0; nt < 8; ++nt)
                #pragma unroll
                for (int c = 0; c < 4; ++c)
                    rsum[mt * 2 + (c >> 1)] += exp2_fast(acc[mt][nt][c]);

        // diagonal lives exactly in the kt == qb tile
        if (kt == qb) {
            #pragma unroll
            for (int mt = 0; mt < 2; ++mt)
                #pragma unroll
                for (int nt = 0; nt < 8; ++nt)
                    #pragma unroll
                    for (int c = 0; c < 4; ++c) {
                        int lr = warp_m * 32 + mt * 16 + (c >> 1) * 8 + (lane >> 2);
                        int lc = warp_n * 64 + nt * 8 + (lane & 3) * 2 + (c & 1);
                        if (lr == lc) rdiag[mt * 2 + (c >> 1)] += acc[mt][nt][c];
                    }
        }
    }

    flush_partials(cur_qb);

    // ---- fused finalize: last CTA out computes the loss ----
    __threadfence();                      // make our atomicAdds visible
    __syncthreads();                      // all threads' adds issued
    __shared__ unsigned int s_is_last;
    if (tid == 0)
        s_is_last = (atomicAdd(&g_done_ctr, 1u) == GRID_SZ - 1) ? 1u : 0u;
    __syncthreads();
    if (s_is_last) {
        __threadfence();                  // acquire side: see all CTAs' adds
        float acc = 0.f;
        for (int r = tid; r < NMAX; r += THREADS)
            acc += LN2 * (log2f(g_psum[r]) - g_pdiag[r]);
        #pragma unroll
        for (int o = 16; o > 0; o >>= 1)
            acc += __shfl_xor_sync(0xffffffffu, acc, o);
        __shared__ float wsum[8];
        if (lane == 0) wsum[warp] = acc;
        __syncthreads();
        if (tid == 0) {
            float tot = 0.f;
            #pragma unroll
            for (int i = 0; i < 8; ++i) tot += wsum[i];
            out[0] = tot / (float)NMAX;
            g_done_ctr = 0;               // reset for next graph replay
        }
    }
}

// ---------------------------------------------------------------------------
extern "C" void kernel_launch(void* const* d_in, const int* in_sizes, int n_in,
                              void* d_out, int out_size) {
    const float* q = (const float*)d_in[0];
    const float* k = (const float*)d_in[1];
    const int N = in_sizes[0] / D;          // 8192
    float* out = (float*)d_out;

    normalize_kernel<<<2 * N / 16, 256>>>(q, k, N);

    size_t smem = DATA_OFF + (size_t)(BM + 2 * BN) * SPAD * sizeof(__nv_bfloat16);
    cudaFuncSetAttribute(infonce_kernel,
                         cudaFuncAttributeMaxDynamicSharedMemorySize, (int)smem);
    infonce_kernel<<<GRID_SZ, THREADS, smem>>>(out);
}

// round 16
// speedup vs baseline: 1.1625x; 1.0175x over previous
#include <cuda_runtime.h>
#include <cuda_bf16.h>
#include <cstdint>

#define D        256
#define NMAX     8192
#define BM       128
#define BN       128
#define QBLKS    (NMAX / BM)             // 64
#define KTILES   (NMAX / BN)             // 64
#define TOT_TILES (QBLKS * KTILES)       // 4096
#define GRID_SZ  148                     // one CTA per SM, balanced static ranges
#define THREADS  256                     // 8 warps, warp grid 4(M) x 2(N)
#define SPAD     264                     // 256 + 8 halves pad: conflict-free LDSM

#define LOG2E    1.4426950408889634f
#define LN2      0.6931471805599453f

// smem: [0..31] mbarriers (full0, full1, empty0, empty1), data from 128
#define MB_FULL0   0
#define MB_FULL1   8
#define MB_EMPTY0  16
#define MB_EMPTY1  24
#define DATA_OFF   128

__device__ __align__(16) __nv_bfloat16 g_Qn[(size_t)NMAX * D];
__device__ __align__(16) __nv_bfloat16 g_Kn[(size_t)NMAX * D];
__device__ float g_psum[NMAX];
__device__ float g_pdiag[NMAX];
__device__ unsigned int g_qb_cnt[QBLKS];   // tiles completed per query block

// ---------------- helpers ----------------
__device__ __forceinline__ void cp_async16(void* smem_dst, const void* gmem_src) {
    uint32_t s = (uint32_t)__cvta_generic_to_shared(smem_dst);
    asm volatile("cp.async.cg.shared.global [%0], [%1], 16;\n" :: "r"(s), "l"(gmem_src));
}
// .noinc: one REAL arrival per thread (init count == #threads).
__device__ __forceinline__ void cp_mbar_arrive_noinc(uint32_t mbar) {
    asm volatile("cp.async.mbarrier.arrive.noinc.shared::cta.b64 [%0];"
                 :: "r"(mbar) : "memory");
}
__device__ __forceinline__ void cp_wait_all() {
    asm volatile("cp.async.wait_group 0;\n" ::: "memory");
}
__device__ __forceinline__ void mbar_init(uint32_t a, uint32_t cnt) {
    asm volatile("mbarrier.init.shared.b64 [%0], %1;" :: "r"(a), "r"(cnt) : "memory");
}
__device__ __forceinline__ void mbar_arrive(uint32_t a) {
    asm volatile("mbarrier.arrive.shared.b64 _, [%0];" :: "r"(a) : "memory");
}
__device__ __forceinline__ void mbar_wait(uint32_t a, uint32_t parity) {
    asm volatile("{\n\t.reg .pred P1;\n\t"
                 "WAIT_LOOP_%=:\n\t"
                 "mbarrier.try_wait.parity.acquire.cta.shared::cta.b64 P1, [%0], %1, 0x989680;\n\t"
                 "@P1 bra.uni WAIT_DONE_%=;\n\t"
                 "bra.uni WAIT_LOOP_%=;\n\t"
                 "WAIT_DONE_%=:\n\t}" :: "r"(a), "r"(parity) : "memory");
}
__device__ __forceinline__ void ldsm_x4(uint32_t& r0, uint32_t& r1,
                                        uint32_t& r2, uint32_t& r3, uint32_t addr) {
    asm volatile("ldmatrix.sync.aligned.m8n8.x4.shared.b16 {%0,%1,%2,%3}, [%4];"
                 : "=r"(r0), "=r"(r1), "=r"(r2), "=r"(r3) : "r"(addr));
}
__device__ __forceinline__ float exp2_fast(float x) {
    float r;
    asm("ex2.approx.ftz.f32 %0, %1;" : "=f"(r) : "f"(x));
    return r;
}

// Load one [128 x 256 bf16] tile into SPAD-padded smem via cp.async (256 thr).
__device__ __forceinline__ void load_tile_async(__nv_bfloat16* s,
                                                const __nv_bfloat16* g, int tid) {
    const uint4* src = (const uint4*)g;
    #pragma unroll
    for (int i = tid; i < BM * 32; i += THREADS) {   // 32 x 16B chunks per row
        int r = i >> 5, c = i & 31;
        cp_async16(s + r * SPAD + c * 8, src + r * 32 + c);
    }
}

// ---------------------------------------------------------------------------
// Kernel 1: L2 normalize (one warp per TWO rows) + zero partials/counters/out.
// Queries get 2*log2(e) folded in -> log2-domain logits, no max needed.
// ---------------------------------------------------------------------------
__global__ void normalize_kernel(const float* __restrict__ q,
                                 const float* __restrict__ k, int N,
                                 float* __restrict__ out) {
    // zero accumulators + per-qb counters + output (same stream, pre-infonce)
    int gid = blockIdx.x * 256 + threadIdx.x;
    if (gid < NMAX) { g_psum[gid] = 0.f; g_pdiag[gid] = 0.f; }
    if (gid < QBLKS) g_qb_cnt[gid] = 0u;
    if (gid == 0) out[0] = 0.f;

    const int warp = threadIdx.x >> 5, lane = threadIdx.x & 31;
    const int row0 = blockIdx.x * 16 + warp * 2;     // grid = 2N/16
    const bool is_q = row0 < N;
    const int  r0   = is_q ? row0 : row0 - N;
    const float* srcb = is_q ? q : k;
    __nv_bfloat16* dstb = is_q ? g_Qn : g_Kn;

    const float4* sA = (const float4*)(srcb + (size_t)r0 * D);
    const float4* sB = (const float4*)(srcb + (size_t)(r0 + 1) * D);
    float4 a0 = sA[lane * 2], a1 = sA[lane * 2 + 1];
    float4 b0 = sB[lane * 2], b1 = sB[lane * 2 + 1];

    float ssA = a0.x*a0.x + a0.y*a0.y + a0.z*a0.z + a0.w*a0.w
              + a1.x*a1.x + a1.y*a1.y + a1.z*a1.z + a1.w*a1.w;
    float ssB = b0.x*b0.x + b0.y*b0.y + b0.z*b0.z + b0.w*b0.w
              + b1.x*b1.x + b1.y*b1.y + b1.z*b1.z + b1.w*b1.w;
    #pragma unroll
    for (int o = 16; o > 0; o >>= 1) {
        ssA += __shfl_xor_sync(0xffffffffu, ssA, o);
        ssB += __shfl_xor_sync(0xffffffffu, ssB, o);
    }

    float scA = rsqrtf(fmaxf(ssA, 1e-24f));
    float scB = rsqrtf(fmaxf(ssB, 1e-24f));
    if (is_q) { scA *= 2.0f * LOG2E; scB *= 2.0f * LOG2E; }

    uint4 oA, oB;
    {
        __nv_bfloat162 t0 = __float22bfloat162_rn({a0.x*scA, a0.y*scA});
        __nv_bfloat162 t1 = __float22bfloat162_rn({a0.z*scA, a0.w*scA});
        __nv_bfloat162 t2 = __float22bfloat162_rn({a1.x*scA, a1.y*scA});
        __nv_bfloat162 t3 = __float22bfloat162_rn({a1.z*scA, a1.w*scA});
        oA.x = *(uint32_t*)&t0; oA.y = *(uint32_t*)&t1;
        oA.z = *(uint32_t*)&t2; oA.w = *(uint32_t*)&t3;
    }
    {
        __nv_bfloat162 t0 = __float22bfloat162_rn({b0.x*scB, b0.y*scB});
        __nv_bfloat162 t1 = __float22bfloat162_rn({b0.z*scB, b0.w*scB});
        __nv_bfloat162 t2 = __float22bfloat162_rn({b1.x*scB, b1.y*scB});
        __nv_bfloat162 t3 = __float22bfloat162_rn({b1.z*scB, b1.w*scB});
        oB.x = *(uint32_t*)&t0; oB.y = *(uint32_t*)&t1;
        oB.z = *(uint32_t*)&t2; oB.w = *(uint32_t*)&t3;
    }
    ((uint4*)(dstb + (size_t)r0 * D))[lane]       = oA;
    ((uint4*)(dstb + (size_t)(r0 + 1) * D))[lane] = oB;
}

// ---------------------------------------------------------------------------
// Kernel 2: bf16 mma.sync GEMM + fused sum(2^logit) + DISTRIBUTED finalize.
// 148 CTAs, balanced static tile ranges (R12 mainloop verbatim). When a CTA
// completes its tiles of a query block, it bumps g_qb_cnt[qb]; the CTA that
// reaches 64 finalizes those 128 rows immediately (overlapping other CTAs'
// remaining MMA work) — no serial whole-N tail.
// ---------------------------------------------------------------------------
__global__ __launch_bounds__(THREADS, 1)
void infonce_kernel(float* __restrict__ out) {
    extern __shared__ __align__(16) char smem_raw[];
    const uint32_t sb = (uint32_t)__cvta_generic_to_shared(smem_raw);
    __nv_bfloat16* As  = (__nv_bfloat16*)(smem_raw + DATA_OFF); // 128 * SPAD
    __nv_bfloat16* Bs0 = As + BM * SPAD;                        // buf 0
    __nv_bfloat16* Bs1 = Bs0 + BN * SPAD;                       // buf 1
    __nv_bfloat16* Bbuf[2] = { Bs0, Bs1 };

    const uint32_t full_mb[2]  = { sb + MB_FULL0,  sb + MB_FULL1 };
    const uint32_t empty_mb[2] = { sb + MB_EMPTY0, sb + MB_EMPTY1 };

    const int tid    = threadIdx.x;
    const int lane   = tid & 31;
    const int warp   = tid >> 5;
    const int warp_m = warp >> 1;       // 0..3 (32 rows each)
    const int warp_n = warp & 1;        // 0..1 (64 cols each)

    const int start = (blockIdx.x * TOT_TILES) / GRID_SZ;
    const int end   = ((blockIdx.x + 1) * TOT_TILES) / GRID_SZ;
    int cur_qb = start >> 6;

    if (tid == 0) {
        mbar_init(full_mb[0], THREADS);  mbar_init(full_mb[1], THREADS);
        mbar_init(empty_mb[0], 8);       mbar_init(empty_mb[1], 8);
    }
    __syncthreads();

    // prologue: A(cur_qb) + B(kt(start)) -> buf0
    load_tile_async(As, g_Qn + (size_t)cur_qb * BM * D, tid);
    load_tile_async(Bs0, g_Kn + (size_t)(start & 63) * BN * D, tid);
    cp_mbar_arrive_noinc(full_mb[0]);

    // ldmatrix addresses (A smem location fixed; contents swap per qb)
    uint32_t a_base[2];
    #pragma unroll
    for (int mt = 0; mt < 2; ++mt)
        a_base[mt] = (uint32_t)__cvta_generic_to_shared(
            As + (warp_m * 32 + mt * 16 + (lane & 15)) * SPAD + (lane >> 4) * 8);
    uint32_t b_row_off[4];                // 4 x 16-col groups = 64 cols per warp
    #pragma unroll
    for (int b = 0; b < 4; ++b)
        b_row_off[b] = (uint32_t)(
            ((warp_n * 64 + b * 16 + ((lane >> 4) & 1) * 8 + (lane & 7)) * SPAD
             + ((lane >> 3) & 1) * 8) * sizeof(__nv_bfloat16));

    // parities: full waits start {0,0}; empty waits start {0,1}
    uint32_t cf0 = 0, cf1 = 0, pe0 = 0, pe1 = 1;

    float rsum[4]  = {0.f, 0.f, 0.f, 0.f};
    float rdiag[4] = {0.f, 0.f, 0.f, 0.f};
    __shared__ unsigned int s_last;
    __shared__ float s_wsum[8];

    // flush partials of qb (quad-shfl + atomicAdd + release fence), then zero
    auto flush_partials = [&](int qb) {
        #pragma unroll
        for (int rs = 0; rs < 4; ++rs) {
            rsum[rs]  += __shfl_xor_sync(0xffffffffu, rsum[rs], 1);
            rsum[rs]  += __shfl_xor_sync(0xffffffffu, rsum[rs], 2);
            rdiag[rs] += __shfl_xor_sync(0xffffffffu, rdiag[rs], 1);
            rdiag[rs] += __shfl_xor_sync(0xffffffffu, rdiag[rs], 2);
        }
        if ((lane & 3) == 0) {
            #pragma unroll
            for (int rs = 0; rs < 4; ++rs) {
                int row = qb * BM + warp_m * 32 + (rs >> 1) * 16
                        + (rs & 1) * 8 + (lane >> 2);
                atomicAdd(&g_psum[row], rsum[rs]);
                atomicAdd(&g_pdiag[row], rdiag[rs]);
            }
            __threadfence();      // release: adds visible before counter bump
        }
        #pragma unroll
        for (int rs = 0; rs < 4; ++rs) { rsum[rs] = 0.f; rdiag[rs] = 0.f; }
    };

    // after finishing all our tiles of qb: bump counter; last toucher
    // finalizes that block's 128 rows and adds to out.
    auto finalize_qb = [&](int qb) {
        int lo = qb * KTILES, hi = lo + KTILES;
        int cnt = min(end, hi) - max(start, lo);   // our tiles in this qb (>0)
        __syncthreads();                            // all warps' flush+fence done
        if (tid == 0)
            s_last = (atomicAdd(&g_qb_cnt[qb], (unsigned)cnt) + (unsigned)cnt
                      == (unsigned)KTILES) ? 1u : 0u;
        __syncthreads();
        if (s_last) {
            __threadfence();                        // acquire: see peers' adds
            float v = 0.f;
            if (tid < BM) {
                int r = qb * BM + tid;
                v = LN2 * (log2f(g_psum[r]) - g_pdiag[r]);
            }
            #pragma unroll
            for (int o = 16; o > 0; o >>= 1)
                v += __shfl_xor_sync(0xffffffffu, v, o);
            if (lane == 0) s_wsum[warp] = v;
            __syncthreads();
            if (tid == 0) {
                float tot = 0.f;
                #pragma unroll
                for (int i = 0; i < 8; ++i) tot += s_wsum[i];
                atomicAdd(out, tot / (float)NMAX);
            }
        }
    };

    for (int t = start; t < end; ++t) {
        const int j  = t - start;
        const int qb = t >> 6;
        const int kt = t & 63;
        const int b  = j & 1;
        const int nb = b ^ 1;

        // qb transition (at most once per CTA): flush + finalize, reload A
        if (qb != cur_qb) {
            flush_partials(cur_qb);
            finalize_qb(cur_qb);
            __syncthreads();     // all warps done with MMA on old A
            load_tile_async(As, g_Qn + (size_t)qb * BM * D, tid);
            cp_wait_all();       // A cps (+ any in-flight B(t) cps) complete
            __syncthreads();
            cur_qb = qb;
        }

        // producer: prefetch B of tile t+1 into buf nb
        if (t + 1 < end) {
            uint32_t pe = nb ? pe1 : pe0;
            mbar_wait(empty_mb[nb], pe);
            if (nb) pe1 ^= 1; else pe0 ^= 1;
            load_tile_async(Bbuf[nb],
                            g_Kn + (size_t)((t + 1) & 63) * BN * D, tid);
            cp_mbar_arrive_noinc(full_mb[nb]);
        }

        // consumer: tile t's B (and A) fully visible
        {
            uint32_t cf = b ? cf1 : cf0;
            mbar_wait(full_mb[b], cf);
            if (b) cf1 ^= 1; else cf0 ^= 1;
        }

        float acc[2][8][4];
        #pragma unroll
        for (int a = 0; a < 2; ++a)
            #pragma unroll
            for (int bb2 = 0; bb2 < 8; ++bb2)
                #pragma unroll
                for (int c = 0; c < 4; ++c) acc[a][bb2][c] = 0.f;

        const uint32_t bb = (uint32_t)__cvta_generic_to_shared(Bbuf[b]);

        #pragma unroll
        for (int ks = 0; ks < D / 16; ++ks) {
            uint32_t af[2][4], bf[16];
            ldsm_x4(af[0][0], af[0][1], af[0][2], af[0][3], a_base[0] + ks * 32);
            ldsm_x4(af[1][0], af[1][1], af[1][2], af[1][3], a_base[1] + ks * 32);
            #pragma unroll
            for (int g = 0; g < 4; ++g)
                ldsm_x4(bf[g * 4], bf[g * 4 + 1], bf[g * 4 + 2], bf[g * 4 + 3],
                        bb + b_row_off[g] + ks * 32);
            #pragma unroll
            for (int mt = 0; mt < 2; ++mt)
                #pragma unroll
                for (int nt = 0; nt < 8; ++nt) {
                    asm volatile(
                        "mma.sync.aligned.m16n8k16.row.col.f32.bf16.bf16.f32 "
                        "{%0,%1,%2,%3}, {%4,%5,%6,%7}, {%8,%9}, {%0,%1,%2,%3};\n"
                        : "+f"(acc[mt][nt][0]), "+f"(acc[mt][nt][1]),
                          "+f"(acc[mt][nt][2]), "+f"(acc[mt][nt][3])
                        : "r"(af[mt][0]), "r"(af[mt][1]),
                          "r"(af[mt][2]), "r"(af[mt][3]),
                          "r"(bf[nt * 2]), "r"(bf[nt * 2 + 1]));
                }
        }

        // done reading buf b -> producers may overwrite it (before epilogue)
        if (lane == 0) mbar_arrive(empty_mb[b]);

        // epilogue: 64 ex2 + adds (no max needed in log2 domain)
        #pragma unroll
        for (int mt = 0; mt < 2; ++mt)
            #pragma unroll
            for (int nt = 0; nt < 8; ++nt)
                #pragma unroll
                for (int c = 0; c < 4; ++c)
                    rsum[mt * 2 + (c >> 1)] += exp2_fast(acc[mt][nt][c]);

        // diagonal lives exactly in the kt == qb tile
        if (kt == qb) {
            #pragma unroll
            for (int mt = 0; mt < 2; ++mt)
                #pragma unroll
                for (int nt = 0; nt < 8; ++nt)
                    #pragma unroll
                    for (int c = 0; c < 4; ++c) {
                        int lr = warp_m * 32 + mt * 16 + (c >> 1) * 8 + (lane >> 2);
                        int lc = warp_n * 64 + nt * 8 + (lane & 3) * 2 + (c & 1);
                        if (lr == lc) rdiag[mt * 2 + (c >> 1)] += acc[mt][nt][c];
                    }
        }
    }

    flush_partials(cur_qb);
    finalize_qb(cur_qb);
}

// ---------------------------------------------------------------------------
extern "C" void kernel_launch(void* const* d_in, const int* in_sizes, int n_in,
                              void* d_out, int out_size) {
    const float* q = (const float*)d_in[0];
    const float* k = (const float*)d_in[1];
    const int N = in_sizes[0] / D;          // 8192
    float* out = (float*)d_out;

    normalize_kernel<<<2 * N / 16, 256>>>(q, k, N, out);

    size_t smem = DATA_OFF + (size_t)(BM + 2 * BN) * SPAD * sizeof(__nv_bfloat16);
    cudaFuncSetAttribute(infonce_kernel,
                         cudaFuncAttributeMaxDynamicSharedMemorySize, (int)smem);
    infonce_kernel<<<GRID_SZ, THREADS, smem>>>(out);
}